// round 3
// baseline (speedup 1.0000x reference)
#include <cuda_runtime.h>

#define NHEAD 4
#define NEG_SLOPE 0.2f

// ---------------- scratch (allocation-free: __device__ globals) ----------------
// B=1024, fanouts 10/25.  y: aggregated features for 10240 level-1 nodes + 1024 roots.
__device__ float g_y  [11264 * NHEAD * 256];  // layer-0 aggregates (both levels)
__device__ float g_h  [11264 * 512];          // layer-0 outputs: h1 rows [0,10240), h0a rows [10240,11264)
__device__ float g_y2 [1024 * NHEAD * 512];   // layer-1 aggregates
__device__ float g_h0b[1024 * 512];           // layer-1 output

// ---------------- f32x2 packed-math helpers (sm_100+) ----------------
__device__ __forceinline__ unsigned long long pack2(float lo, float hi) {
    unsigned long long r;
    asm("mov.b64 %0, {%1,%2};" : "=l"(r) : "f"(lo), "f"(hi));
    return r;
}
__device__ __forceinline__ void unpack2(unsigned long long v, float& lo, float& hi) {
    asm("mov.b64 {%0,%1}, %2;" : "=f"(lo), "=f"(hi) : "l"(v));
}
__device__ __forceinline__ void fma2(unsigned long long& c, unsigned long long a,
                                     unsigned long long b) {
    asm("fma.rn.f32x2 %0, %1, %2, %0;" : "+l"(c) : "l"(a), "l"(b));
}

// ---------------- fused attention + aggregation ----------------
// One CTA per item; supports two item groups (different self/neigh tensors and S)
// in one launch. a-vectors live in registers (8 f-slots per lane per head, chunked
// by 256 features). Writes y[item][h][f] (h-major per item).
template <int F>
__global__ __launch_bounds__(256)
void gat_attn(const float* __restrict__ xsA, const float* __restrict__ xnA, int SA, int nA,
              const float* __restrict__ xsB, const float* __restrict__ xnB, int SB,
              const float* __restrict__ a_self, const float* __restrict__ a_neigh,
              float* __restrict__ y)
{
    constexpr int RCAP = (F == 256) ? 26 : 11;   // max rows staged (S+1)
    extern __shared__ float sm[];
    float* sx     = sm;                 // (S+1)*F rows: [self; neighbors]
    float* slog   = sm + RCAP * F;      // RCAP*4 logits->attn, layout [s][h]
    float* slself = slog + RCAP * 4;    // 4

    const int tid = threadIdx.x;
    const int w = tid >> 5, l = tid & 31;
    const int item = blockIdx.x;

    const float* xs; const float* xn; int S;
    if (item < nA) { xs = xsA + (long)item * F;        xn = xnA + (long)item * SA * F;        S = SA; }
    else           { int b = item - nA;
                     xs = xsB + (long)b * F;           xn = xnB + (long)b * SB * F;           S = SB; }
    float* yo = y + (long)item * NHEAD * F;

    // stage x_all = [self; neighbors] into smem
    {
        const float4* s4 = (const float4*)xs;
        for (int i = tid; i < F / 4; i += 256) ((float4*)sx)[i] = s4[i];
        const float4* n4 = (const float4*)xn;
        float4* dst = (float4*)(sx + F);
        for (int i = tid; i < S * F / 4; i += 256) dst[i] = n4[i];
    }

    // self logits (warp 0, straight from global — L1/L2 hot)
    if (w == 0) {
        float sl[4] = {0.f, 0.f, 0.f, 0.f};
        for (int c = 0; c < F / 256; c++) {
            #pragma unroll
            for (int fi = 0; fi < 8; fi++) {
                const int f = c * 256 + l + fi * 32;
                const float xv = xs[f];
                sl[0] += xv * a_self[0 * F + f];
                sl[1] += xv * a_self[1 * F + f];
                sl[2] += xv * a_self[2 * F + f];
                sl[3] += xv * a_self[3 * F + f];
            }
        }
        #pragma unroll
        for (int h = 0; h < 4; h++) {
            float v = sl[h];
            #pragma unroll
            for (int o = 16; o; o >>= 1) v += __shfl_down_sync(0xffffffffu, v, o);
            if (l == 0) slself[h] = v;
        }
    }
    __syncthreads();

    // neighbor-side logits: row t (0..S) . a_neigh[h], a_neigh held in registers
    {
        float lg[4][4] = {};
        for (int c = 0; c < F / 256; c++) {
            float avn[4][8];
            #pragma unroll
            for (int h = 0; h < 4; h++)
                #pragma unroll
                for (int fi = 0; fi < 8; fi++)
                    avn[h][fi] = a_neigh[h * F + c * 256 + l + fi * 32];
            #pragma unroll
            for (int ti = 0; ti < 4; ti++) {
                const int t = w + ti * 8;
                if (t <= S) {
                    const float* row = sx + t * F + c * 256;
                    #pragma unroll
                    for (int fi = 0; fi < 8; fi++) {
                        const float xv = row[l + fi * 32];
                        lg[ti][0] += xv * avn[0][fi];
                        lg[ti][1] += xv * avn[1][fi];
                        lg[ti][2] += xv * avn[2][fi];
                        lg[ti][3] += xv * avn[3][fi];
                    }
                }
            }
        }
        #pragma unroll
        for (int ti = 0; ti < 4; ti++) {
            const int t = w + ti * 8;
            #pragma unroll
            for (int h = 0; h < 4; h++) {
                float v = lg[ti][h];
                #pragma unroll
                for (int o = 16; o; o >>= 1) v += __shfl_down_sync(0xffffffffu, v, o);
                if (l == 0 && t <= S) slog[t * 4 + h] = v;
            }
        }
    }
    __syncthreads();

    // leaky-relu + softmax over S+1, one warp (lane = s)
    if (tid < 32) {
        const bool act = (l <= S);
        float z[4];
        #pragma unroll
        for (int h = 0; h < 4; h++) {
            float v = act ? (slself[h] + slog[l * 4 + h]) : -1e30f;
            z[h] = (v >= 0.f) ? v : NEG_SLOPE * v;
        }
        #pragma unroll
        for (int h = 0; h < 4; h++) {
            float m = z[h];
            #pragma unroll
            for (int o = 16; o; o >>= 1) m = fmaxf(m, __shfl_xor_sync(0xffffffffu, m, o));
            const float ev = act ? __expf(z[h] - m) : 0.f;
            float s = ev;
            #pragma unroll
            for (int o = 16; o; o >>= 1) s += __shfl_xor_sync(0xffffffffu, s, o);
            if (act) slog[l * 4 + h] = ev / s;
        }
    }
    __syncthreads();

    // aggregation: y[h][f] = sum_s attn[s][h] * x_all[s][f]
    for (int f = tid; f < F; f += 256) {
        float a0 = 0.f, a1 = 0.f, a2 = 0.f, a3 = 0.f;
        for (int s = 0; s <= S; s++) {
            const float xv = sx[s * F + f];
            const float4 at = *(const float4*)(slog + s * 4);   // broadcast LDS.128
            a0 += at.x * xv; a1 += at.y * xv; a2 += at.z * xv; a3 += at.w * xv;
        }
        yo[0 * F + f] = a0; yo[1 * F + f] = a1; yo[2 * F + f] = a2; yo[3 * F + f] = a3;
    }
}

// ---------------- f32x2 tiled GEMM, packed-B smem, double-buffered ----------------
// C[m][h*cColPerH + n] = sum_k A[h*aStrideH + m*lda + k] * B[h*bStrideH + k*ldb + n]
template<int BM, int BN, int TM, int TN>
__global__ __launch_bounds__(256)
void gemm_f32x2(const float* __restrict__ A, const float* __restrict__ B,
                float* __restrict__ C,
                int K, int lda, int ldb, int ldc,
                int aStrideH, int bStrideH, int cColPerH)
{
    constexpr int BK  = 16;
    constexpr int NT  = 256;
    constexpr int TX  = BN / TN;
    constexpr int MP  = TM / 2;
    constexpr int nA4 = BM * BK / 4 / NT;
    constexpr int nB4 = BK * BN / 4 / NT;

    const int h = blockIdx.z;
    A += (long)h * aStrideH;
    B += (long)h * bStrideH;
    const int bm = blockIdx.x * BM;
    const int bn = blockIdx.y * BN;

    __shared__ float As[2][BK][BM];                              // transposed: As[k][m]
    __shared__ __align__(16) unsigned long long Bs[2][BK][BN];   // each entry = (b,b) packed

    const int tid = threadIdx.x;
    const int tx  = tid % TX;
    const int ty  = tid / TX;

    unsigned long long acc[MP][TN];
    #pragma unroll
    for (int i = 0; i < MP; i++)
        #pragma unroll
        for (int j = 0; j < TN; j++) acc[i][j] = 0ull;

    int arow[nA4], akq[nA4], bkk[nB4], bnn[nB4];
    #pragma unroll
    for (int i = 0; i < nA4; i++) {
        const int id = tid + i * NT;
        arow[i] = id / (BK / 4);
        akq[i]  = (id % (BK / 4)) * 4;
    }
    #pragma unroll
    for (int i = 0; i < nB4; i++) {
        const int id = tid + i * NT;
        bkk[i] = id / (BN / 4);
        bnn[i] = (id % (BN / 4)) * 4;
    }

    float4 ra[nA4], rb[nB4];
    const int nk = K / BK;

    auto ldg = [&](int kb) {
        #pragma unroll
        for (int i = 0; i < nA4; i++)
            ra[i] = *(const float4*)(A + (long)(bm + arow[i]) * lda + kb * BK + akq[i]);
        #pragma unroll
        for (int i = 0; i < nB4; i++)
            rb[i] = *(const float4*)(B + (long)(kb * BK + bkk[i]) * ldb + bn + bnn[i]);
    };
    auto sts = [&](int s) {
        #pragma unroll
        for (int i = 0; i < nA4; i++) {
            As[s][akq[i] + 0][arow[i]] = ra[i].x;
            As[s][akq[i] + 1][arow[i]] = ra[i].y;
            As[s][akq[i] + 2][arow[i]] = ra[i].z;
            As[s][akq[i] + 3][arow[i]] = ra[i].w;
        }
        #pragma unroll
        for (int i = 0; i < nB4; i++) {
            unsigned long long* bq = &Bs[s][bkk[i]][bnn[i]];
            ulonglong2 p0, p1;
            p0.x = pack2(rb[i].x, rb[i].x); p0.y = pack2(rb[i].y, rb[i].y);
            p1.x = pack2(rb[i].z, rb[i].z); p1.y = pack2(rb[i].w, rb[i].w);
            *(ulonglong2*)bq       = p0;
            *(ulonglong2*)(bq + 2) = p1;
        }
    };
    auto compute = [&](int s) {
        #pragma unroll
        for (int k = 0; k < BK; k++) {
            float4 a4[TM / 4];
            #pragma unroll
            for (int q = 0; q < TM / 4; q++)
                a4[q] = *(const float4*)&As[s][k][ty * TM + q * 4];
            unsigned long long ap[MP];
            #pragma unroll
            for (int q = 0; q < TM / 4; q++) {
                ap[2 * q]     = pack2(a4[q].x, a4[q].y);   // folds to reg-pair view
                ap[2 * q + 1] = pack2(a4[q].z, a4[q].w);
            }
            unsigned long long bp[TN];
            #pragma unroll
            for (int q = 0; q < TN / 2; q++) {
                const ulonglong2 bb = *(const ulonglong2*)&Bs[s][k][tx * TN + 2 * q];
                bp[2 * q] = bb.x; bp[2 * q + 1] = bb.y;
            }
            #pragma unroll
            for (int i = 0; i < MP; i++)
                #pragma unroll
                for (int j = 0; j < TN; j++)
                    fma2(acc[i][j], ap[i], bp[j]);
        }
    };

    ldg(0);
    sts(0);
    __syncthreads();

    for (int kb = 0; kb < nk; kb++) {
        const int cur = kb & 1;
        if (kb + 1 < nk) ldg(kb + 1);
        compute(cur);
        if (kb + 1 < nk) {
            sts(cur ^ 1);
            __syncthreads();
        }
    }

    const int ccol = bn + h * cColPerH;
    #pragma unroll
    for (int ip = 0; ip < MP; ip++) {
        float lo[TN], hi[TN];
        #pragma unroll
        for (int j = 0; j < TN; j++) unpack2(acc[ip][j], lo[j], hi[j]);
        float* cr0 = C + (long)(bm + ty * TM + 2 * ip)     * ldc + ccol + tx * TN;
        float* cr1 = C + (long)(bm + ty * TM + 2 * ip + 1) * ldc + ccol + tx * TN;
        #pragma unroll
        for (int q = 0; q < TN / 4; q++) {
            *(float4*)(cr0 + q * 4) = make_float4(lo[q*4+0], lo[q*4+1], lo[q*4+2], lo[q*4+3]);
            *(float4*)(cr1 + q * 4) = make_float4(hi[q*4+0], hi[q*4+1], hi[q*4+2], hi[q*4+3]);
        }
    }
}

// ---------------- launch ----------------
static float* sym_addr(const void* symbol)
{
    void* p = nullptr;
    cudaGetSymbolAddress(&p, symbol);
    return (float*)p;
}

extern "C" void kernel_launch(void* const* d_in, const int* in_sizes, int n_in,
                              void* d_out, int out_size)
{
    const float* x0  = (const float*)d_in[0];  // (B, 1, 256)
    const float* x1  = (const float*)d_in[1];  // (B, 10, 256)
    const float* x2  = (const float*)d_in[2];  // (B, 250, 256)
    const float* w0  = (const float*)d_in[3];  // (4, 256, 128)
    const float* a0s = (const float*)d_in[4];  // (4, 256)
    const float* a0n = (const float*)d_in[5];  // (4, 256)
    const float* w1  = (const float*)d_in[6];  // (4, 512, 128)
    const float* a1s = (const float*)d_in[7];  // (4, 512)
    const float* a1n = (const float*)d_in[8];  // (4, 512)
    const float* fcw = (const float*)d_in[9];  // (512, 256)
    float* out = (float*)d_out;                // (B, 256)

    const int Bn = in_sizes[0] / 256;          // 1024
    const int nA = Bn * 10;                    // 10240 level-1 nodes
    const int nTot = nA + Bn;                  // 11264

    float* y   = sym_addr(g_y);
    float* hb  = sym_addr(g_h);
    float* y2  = sym_addr(g_y2);
    float* h0b = sym_addr(g_h0b);

    // ---- layer-0 attention at both tree levels, one launch ----
    {
        const size_t smem = (size_t)(26 * 256 + 26 * 4 + 8) * sizeof(float);
        gat_attn<256><<<nTot, 256, smem>>>(x1, x2, 25, nA,
                                           x0, x1, 10,
                                           a0s, a0n, y);
    }
    // ---- layer-0 projection for all 11264 nodes: hb = y @ w0 (per head) ----
    gemm_f32x2<64, 128, 4, 8><<<dim3(nTot / 64, 1, NHEAD), 256>>>(
        y, w0, hb, 256, NHEAD * 256, 128, 512, 256, 256 * 128, 128);

    // ---- layer-1 attention at root level: y2 = attn-agg(h0a, h1; a1) ----
    {
        const size_t smem = (size_t)(11 * 512 + 11 * 4 + 8) * sizeof(float);
        gat_attn<512><<<Bn, 256, smem>>>(hb + (long)nA * 512, hb, 10, Bn,
                                         hb + (long)nA * 512, hb, 10,
                                         a1s, a1n, y2);
    }
    // ---- layer-1 projection: h0b = y2 @ w1 (per head) ----
    gemm_f32x2<64, 64, 4, 4><<<dim3(Bn / 64, 2, NHEAD), 256>>>(
        y2, w1, h0b, 512, NHEAD * 512, 128, 512, 512, 512 * 128, 128);

    // ---- final projection: out = h0b @ fc_w ----
    gemm_f32x2<64, 64, 4, 4><<<dim3(Bn / 64, 4, 1), 256>>>(
        h0b, fcw, out, 512, 512, 256, 256, 0, 0, 0);
}

// round 4
// speedup vs baseline: 2.1632x; 2.1632x over previous
#include <cuda_runtime.h>

#define NHEAD 4
#define NEG_SLOPE 0.2f

// ---------------- scratch (allocation-free: __device__ globals) ----------------
// B=1024, fanouts 10/25.
__device__ float g_y  [11264 * NHEAD * 256];  // layer-0 aggregates (both levels)
__device__ float g_h  [11264 * 512];          // layer-0 outputs: h1 rows [0,10240), h0a rows [10240,11264)
__device__ float g_y2 [1024 * NHEAD * 512];   // layer-1 aggregates
__device__ float g_h0b[1024 * 512];           // layer-1 output

// ---------------- f32x2 packed-math helpers (sm_100+) ----------------
__device__ __forceinline__ unsigned long long pack2(float lo, float hi) {
    unsigned long long r;
    asm("mov.b64 %0, {%1,%2};" : "=l"(r) : "f"(lo), "f"(hi));
    return r;
}
__device__ __forceinline__ void unpack2(unsigned long long v, float& lo, float& hi) {
    asm("mov.b64 {%0,%1}, %2;" : "=f"(lo), "=f"(hi) : "l"(v));
}
__device__ __forceinline__ void fma2(unsigned long long& c, unsigned long long a,
                                     unsigned long long b) {
    asm("fma.rn.f32x2 %0, %1, %2, %0;" : "+l"(c) : "l"(a), "l"(b));
}

// ---------------- fused attention + aggregation (round-2 proven body) ----------------
// One CTA per item; two item groups (different tensors / S) per launch.
template <int F>
__global__ __launch_bounds__(256)
void gat_attn_agg(const float* __restrict__ xsA, const float* __restrict__ xnA, int SA, int nA,
                  const float* __restrict__ xsB, const float* __restrict__ xnB, int SB,
                  const float* __restrict__ a_self, const float* __restrict__ a_neigh,
                  float* __restrict__ y)
{
    extern __shared__ float sm[];
    const int item = blockIdx.x;
    const int tid  = threadIdx.x;
    const int NT   = 256;

    const float* xsP; const float* xnP; int S;
    if (item < nA) { xsP = xsA + (long)item * F;         xnP = xnA + (long)item * SA * F;         S = SA; }
    else           { const int b = item - nA;
                     xsP = xsB + (long)b * F;            xnP = xnB + (long)b * SB * F;            S = SB; }

    float* sx     = sm;                       // (S+1)*F   : x_all rows
    float* sanb   = sx   + (S + 1) * F;       // NHEAD*F   : a_neigh
    float* sasf   = sanb + NHEAD * F;         // NHEAD*F   : a_self
    float* slog   = sasf + NHEAD * F;         // (S+1)*NHEAD : logits -> attn
    float* slself = slog + (S + 1) * NHEAD;   // NHEAD

    for (int i = tid; i < NHEAD * F; i += NT) { sanb[i] = a_neigh[i]; sasf[i] = a_self[i]; }
    {
        const float4* xs4 = (const float4*)xsP;
        for (int i = tid; i < F / 4; i += NT) ((float4*)sx)[i] = xs4[i];
        const float4* xn4 = (const float4*)xnP;
        float4* dst = (float4*)(sx + F);
        for (int i = tid; i < S * F / 4; i += NT) dst[i] = xn4[i];
    }
    __syncthreads();

    const int w = tid >> 5, l = tid & 31;
    for (int t = w; t < S + 2; t += 8) {
        const float* row = (t < S + 1) ? (sx + t * F) : sx;
        const float* av  = (t < S + 1) ? sanb : sasf;
        float a0 = 0.f, a1 = 0.f, a2 = 0.f, a3 = 0.f;
        for (int f = l; f < F; f += 32) {
            float xv = row[f];
            a0 += xv * av[0 * F + f];
            a1 += xv * av[1 * F + f];
            a2 += xv * av[2 * F + f];
            a3 += xv * av[3 * F + f];
        }
        #pragma unroll
        for (int o = 16; o > 0; o >>= 1) {
            a0 += __shfl_down_sync(0xffffffffu, a0, o);
            a1 += __shfl_down_sync(0xffffffffu, a1, o);
            a2 += __shfl_down_sync(0xffffffffu, a2, o);
            a3 += __shfl_down_sync(0xffffffffu, a3, o);
        }
        if (l == 0) {
            if (t < S + 1) {
                slog[t * NHEAD + 0] = a0; slog[t * NHEAD + 1] = a1;
                slog[t * NHEAD + 2] = a2; slog[t * NHEAD + 3] = a3;
            } else {
                slself[0] = a0; slself[1] = a1; slself[2] = a2; slself[3] = a3;
            }
        }
    }
    __syncthreads();

    if (tid < NHEAD) {
        const int h = tid;
        const float ls = slself[h];
        float m = -1e30f;
        for (int s = 0; s <= S; s++) {
            float z = ls + slog[s * NHEAD + h];
            z = (z >= 0.f) ? z : NEG_SLOPE * z;
            slog[s * NHEAD + h] = z;
            m = fmaxf(m, z);
        }
        float sum = 0.f;
        for (int s = 0; s <= S; s++) {
            float e = __expf(slog[s * NHEAD + h] - m);
            slog[s * NHEAD + h] = e;
            sum += e;
        }
        const float inv = 1.f / sum;
        for (int s = 0; s <= S; s++) slog[s * NHEAD + h] *= inv;
    }
    __syncthreads();

    float* yo = y + (long)item * NHEAD * F;
    for (int f = tid; f < F; f += NT) {
        float a0 = 0.f, a1 = 0.f, a2 = 0.f, a3 = 0.f;
        for (int s = 0; s <= S; s++) {
            const float xv = sx[s * F + f];
            const float* at = slog + s * NHEAD;
            a0 += at[0] * xv; a1 += at[1] * xv; a2 += at[2] * xv; a3 += at[3] * xv;
        }
        yo[0 * F + f] = a0; yo[1 * F + f] = a1; yo[2 * F + f] = a2; yo[3 * F + f] = a3;
    }
}

// ---------------- f32x2 tiled GEMM (round-2 proven version) ----------------
// C[m][h*cColPerH + n] = sum_k A[h*aStrideH + m*lda + k] * B[h*bStrideH + k*ldb + n]
template<int BM, int BN, int TM, int TN>
__global__ __launch_bounds__(256)
void gemm_f32x2(const float* __restrict__ A, const float* __restrict__ B,
                float* __restrict__ C,
                int K, int lda, int ldb, int ldc,
                int aStrideH, int bStrideH, int cColPerH)
{
    constexpr int BK  = 16;
    constexpr int NT  = 256;
    constexpr int TX  = BN / TN;
    constexpr int MP  = TM / 2;
    constexpr int nA4 = BM * BK / 4 / NT;
    constexpr int nB4 = BK * BN / 4 / NT;

    const int h = blockIdx.z;
    A += (long)h * aStrideH;
    B += (long)h * bStrideH;
    const int bm = blockIdx.x * BM;
    const int bn = blockIdx.y * BN;

    __shared__ float As[2][BK][BM];   // transposed A tile: As[k][m]
    __shared__ float Bs[2][BK][BN];

    const int tid = threadIdx.x;
    const int tx  = tid % TX;
    const int ty  = tid / TX;

    unsigned long long acc[MP][TN];
    #pragma unroll
    for (int i = 0; i < MP; i++)
        #pragma unroll
        for (int j = 0; j < TN; j++) acc[i][j] = 0ull;

    int arow[nA4], akq[nA4], bkk[nB4], bnn[nB4];
    #pragma unroll
    for (int i = 0; i < nA4; i++) {
        const int id = tid + i * NT;
        arow[i] = id / (BK / 4);
        akq[i]  = (id % (BK / 4)) * 4;
    }
    #pragma unroll
    for (int i = 0; i < nB4; i++) {
        const int id = tid + i * NT;
        bkk[i] = id / (BN / 4);
        bnn[i] = (id % (BN / 4)) * 4;
    }

    float4 ra[nA4], rb[nB4];
    const int nk = K / BK;

    auto ldg = [&](int kb) {
        #pragma unroll
        for (int i = 0; i < nA4; i++)
            ra[i] = *(const float4*)(A + (long)(bm + arow[i]) * lda + kb * BK + akq[i]);
        #pragma unroll
        for (int i = 0; i < nB4; i++)
            rb[i] = *(const float4*)(B + (long)(kb * BK + bkk[i]) * ldb + bn + bnn[i]);
    };
    auto sts = [&](int s) {
        #pragma unroll
        for (int i = 0; i < nA4; i++) {
            As[s][akq[i] + 0][arow[i]] = ra[i].x;
            As[s][akq[i] + 1][arow[i]] = ra[i].y;
            As[s][akq[i] + 2][arow[i]] = ra[i].z;
            As[s][akq[i] + 3][arow[i]] = ra[i].w;
        }
        #pragma unroll
        for (int i = 0; i < nB4; i++)
            *(float4*)&Bs[s][bkk[i]][bnn[i]] = rb[i];
    };
    auto compute = [&](int s) {
        #pragma unroll
        for (int k = 0; k < BK; k++) {
            float a[TM], b[TN];
            #pragma unroll
            for (int q = 0; q < TM / 4; q++)
                *(float4*)&a[q * 4] = *(const float4*)&As[s][k][ty * TM + q * 4];
            #pragma unroll
            for (int q = 0; q < TN / 4; q++)
                *(float4*)&b[q * 4] = *(const float4*)&Bs[s][k][tx * TN + q * 4];
            unsigned long long ap[MP], bp[TN];
            #pragma unroll
            for (int i = 0; i < MP; i++) ap[i] = pack2(a[2 * i], a[2 * i + 1]);
            #pragma unroll
            for (int j = 0; j < TN; j++) bp[j] = pack2(b[j], b[j]);
            #pragma unroll
            for (int i = 0; i < MP; i++)
                #pragma unroll
                for (int j = 0; j < TN; j++)
                    fma2(acc[i][j], ap[i], bp[j]);
        }
    };

    ldg(0);
    sts(0);
    __syncthreads();

    for (int kb = 0; kb < nk; kb++) {
        const int cur = kb & 1;
        if (kb + 1 < nk) ldg(kb + 1);
        compute(cur);
        if (kb + 1 < nk) {
            sts(cur ^ 1);
            __syncthreads();
        }
    }

    const int ccol = bn + h * cColPerH;
    #pragma unroll
    for (int ip = 0; ip < MP; ip++) {
        float lo[TN], hi[TN];
        #pragma unroll
        for (int j = 0; j < TN; j++) unpack2(acc[ip][j], lo[j], hi[j]);
        float* cr0 = C + (long)(bm + ty * TM + 2 * ip)     * ldc + ccol + tx * TN;
        float* cr1 = C + (long)(bm + ty * TM + 2 * ip + 1) * ldc + ccol + tx * TN;
        #pragma unroll
        for (int q = 0; q < TN / 4; q++) {
            *(float4*)(cr0 + q * 4) = make_float4(lo[q*4+0], lo[q*4+1], lo[q*4+2], lo[q*4+3]);
            *(float4*)(cr1 + q * 4) = make_float4(hi[q*4+0], hi[q*4+1], hi[q*4+2], hi[q*4+3]);
        }
    }
}

// ---------------- launch ----------------
static float* sym_addr(const void* symbol)
{
    void* p = nullptr;
    cudaGetSymbolAddress(&p, symbol);
    return (float*)p;
}

extern "C" void kernel_launch(void* const* d_in, const int* in_sizes, int n_in,
                              void* d_out, int out_size)
{
    const float* x0  = (const float*)d_in[0];  // (B, 1, 256)
    const float* x1  = (const float*)d_in[1];  // (B, 10, 256)
    const float* x2  = (const float*)d_in[2];  // (B, 250, 256)
    const float* w0  = (const float*)d_in[3];  // (4, 256, 128)
    const float* a0s = (const float*)d_in[4];  // (4, 256)
    const float* a0n = (const float*)d_in[5];  // (4, 256)
    const float* w1  = (const float*)d_in[6];  // (4, 512, 128)
    const float* a1s = (const float*)d_in[7];  // (4, 512)
    const float* a1n = (const float*)d_in[8];  // (4, 512)
    const float* fcw = (const float*)d_in[9];  // (512, 256)
    float* out = (float*)d_out;                // (B, 256)

    const int Bn   = in_sizes[0] / 256;        // 1024
    const int nA   = Bn * 10;                  // 10240 level-1 nodes
    const int nTot = nA + Bn;                  // 11264

    float* y   = sym_addr(g_y);
    float* hb  = sym_addr(g_h);
    float* y2  = sym_addr(g_y2);
    float* h0b = sym_addr(g_h0b);

    // ---- layer-0 attention at both tree levels, one launch ----
    {
        const size_t smem = (size_t)(26 * 256 + 2 * NHEAD * 256 + 26 * NHEAD + NHEAD) * 4;
        gat_attn_agg<256><<<nTot, 256, smem>>>(x1, x2, 25, nA,
                                               x0, x1, 10,
                                               a0s, a0n, y);
    }
    // ---- layer-0 projection for all 11264 nodes: hb = y @ w0 (per head) ----
    gemm_f32x2<128, 128, 8, 8><<<dim3(nTot / 128, 1, NHEAD), 256>>>(
        y, w0, hb, 256, NHEAD * 256, 128, 512, 256, 256 * 128, 128);

    // ---- layer-1 attention at root level ----
    {
        const size_t smem = (size_t)(11 * 512 + 2 * NHEAD * 512 + 11 * NHEAD + NHEAD) * 4;
        gat_attn_agg<512><<<Bn, 256, smem>>>(hb + (long)nA * 512, hb, 10, Bn,
                                             hb + (long)nA * 512, hb, 10,
                                             a1s, a1n, y2);
    }
    // ---- layer-1 projection: h0b = y2 @ w1 (per head) ----
    gemm_f32x2<64, 64, 4, 4><<<dim3(Bn / 64, 2, NHEAD), 256>>>(
        y2, w1, h0b, 512, NHEAD * 512, 128, 512, 512, 512 * 128, 128);

    // ---- final projection: out = h0b @ fc_w ----
    gemm_f32x2<64, 64, 4, 4><<<dim3(Bn / 64, 4, 1), 256>>>(
        h0b, fcw, out, 512, 512, 256, 256, 0, 0, 0);
}

// round 5
// speedup vs baseline: 2.1815x; 1.0084x over previous
#include <cuda_runtime.h>

#define NHEAD 4
#define NEG_SLOPE 0.2f

// ---------------- scratch (allocation-free: __device__ globals) ----------------
__device__ float g_y   [11264 * NHEAD * 256];  // layer-0 aggregates (both levels)
__device__ float g_h   [11264 * 512];          // layer-0 outputs: h1 [0,10240), h0a [10240,11264)
__device__ float g_y2  [1024 * NHEAD * 512];   // layer-1 aggregates
__device__ float g_W2  [NHEAD * 512 * 256];    // folded weights: W2[h] = w1[h] @ fcw[h-slice]
__device__ float g_part[NHEAD * 1024 * 256];   // per-head partial outputs

// ---------------- f32x2 packed-math helpers ----------------
__device__ __forceinline__ unsigned long long pack2(float lo, float hi) {
    unsigned long long r;
    asm("mov.b64 %0, {%1,%2};" : "=l"(r) : "f"(lo), "f"(hi));
    return r;
}
__device__ __forceinline__ void unpack2(unsigned long long v, float& lo, float& hi) {
    asm("mov.b64 {%0,%1}, %2;" : "=f"(lo), "=f"(hi) : "l"(v));
}
__device__ __forceinline__ void fma2(unsigned long long& c, unsigned long long a,
                                     unsigned long long b) {
    asm("fma.rn.f32x2 %0, %1, %2, %0;" : "+l"(c) : "l"(a), "l"(b));
}

// ---------------- fused attention + aggregation (round-3 proven, low-LDS) ----------------
// One CTA per item; two item groups per launch. a-vectors held in registers.
template <int F>
__global__ __launch_bounds__(256)
void gat_attn(const float* __restrict__ xsA, const float* __restrict__ xnA, int SA, int nA,
              const float* __restrict__ xsB, const float* __restrict__ xnB, int SB,
              const float* __restrict__ a_self, const float* __restrict__ a_neigh,
              float* __restrict__ y)
{
    constexpr int RCAP = (F == 256) ? 26 : 11;   // max rows staged (S+1)
    extern __shared__ float sm[];
    float* sx     = sm;                 // (S+1)*F rows: [self; neighbors]
    float* slog   = sm + RCAP * F;      // RCAP*4 logits->attn, layout [s][h]
    float* slself = slog + RCAP * 4;    // 4

    const int tid = threadIdx.x;
    const int w = tid >> 5, l = tid & 31;
    const int item = blockIdx.x;

    const float* xs; const float* xn; int S;
    if (item < nA) { xs = xsA + (long)item * F;        xn = xnA + (long)item * SA * F;        S = SA; }
    else           { int b = item - nA;
                     xs = xsB + (long)b * F;           xn = xnB + (long)b * SB * F;           S = SB; }
    float* yo = y + (long)item * NHEAD * F;

    // stage x_all = [self; neighbors] into smem
    {
        const float4* s4 = (const float4*)xs;
        for (int i = tid; i < F / 4; i += 256) ((float4*)sx)[i] = s4[i];
        const float4* n4 = (const float4*)xn;
        float4* dst = (float4*)(sx + F);
        for (int i = tid; i < S * F / 4; i += 256) dst[i] = n4[i];
    }

    // self logits (warp 0, straight from global — L1/L2 hot)
    if (w == 0) {
        float sl[4] = {0.f, 0.f, 0.f, 0.f};
        for (int c = 0; c < F / 256; c++) {
            #pragma unroll
            for (int fi = 0; fi < 8; fi++) {
                const int f = c * 256 + l + fi * 32;
                const float xv = xs[f];
                sl[0] += xv * a_self[0 * F + f];
                sl[1] += xv * a_self[1 * F + f];
                sl[2] += xv * a_self[2 * F + f];
                sl[3] += xv * a_self[3 * F + f];
            }
        }
        #pragma unroll
        for (int h = 0; h < 4; h++) {
            float v = sl[h];
            #pragma unroll
            for (int o = 16; o; o >>= 1) v += __shfl_down_sync(0xffffffffu, v, o);
            if (l == 0) slself[h] = v;
        }
    }
    __syncthreads();

    // neighbor-side logits: row t (0..S) . a_neigh[h], a_neigh in registers
    {
        float lg[4][4] = {};
        for (int c = 0; c < F / 256; c++) {
            float avn[4][8];
            #pragma unroll
            for (int h = 0; h < 4; h++)
                #pragma unroll
                for (int fi = 0; fi < 8; fi++)
                    avn[h][fi] = a_neigh[h * F + c * 256 + l + fi * 32];
            #pragma unroll
            for (int ti = 0; ti < 4; ti++) {
                const int t = w + ti * 8;
                if (t <= S) {
                    const float* row = sx + t * F + c * 256;
                    #pragma unroll
                    for (int fi = 0; fi < 8; fi++) {
                        const float xv = row[l + fi * 32];
                        lg[ti][0] += xv * avn[0][fi];
                        lg[ti][1] += xv * avn[1][fi];
                        lg[ti][2] += xv * avn[2][fi];
                        lg[ti][3] += xv * avn[3][fi];
                    }
                }
            }
        }
        #pragma unroll
        for (int ti = 0; ti < 4; ti++) {
            const int t = w + ti * 8;
            #pragma unroll
            for (int h = 0; h < 4; h++) {
                float v = lg[ti][h];
                #pragma unroll
                for (int o = 16; o; o >>= 1) v += __shfl_down_sync(0xffffffffu, v, o);
                if (l == 0 && t <= S) slog[t * 4 + h] = v;
            }
        }
    }
    __syncthreads();

    // leaky-relu + softmax over S+1, one warp (lane = s)
    if (tid < 32) {
        const bool act = (l <= S);
        float z[4];
        #pragma unroll
        for (int h = 0; h < 4; h++) {
            float v = act ? (slself[h] + slog[l * 4 + h]) : -1e30f;
            z[h] = (v >= 0.f) ? v : NEG_SLOPE * v;
        }
        #pragma unroll
        for (int h = 0; h < 4; h++) {
            float m = z[h];
            #pragma unroll
            for (int o = 16; o; o >>= 1) m = fmaxf(m, __shfl_xor_sync(0xffffffffu, m, o));
            const float ev = act ? __expf(z[h] - m) : 0.f;
            float s = ev;
            #pragma unroll
            for (int o = 16; o; o >>= 1) s += __shfl_xor_sync(0xffffffffu, s, o);
            if (act) slog[l * 4 + h] = ev / s;
        }
    }
    __syncthreads();

    // aggregation: y[h][f] = sum_s attn[s][h] * x_all[s][f]
    for (int f = tid; f < F; f += 256) {
        float a0 = 0.f, a1 = 0.f, a2 = 0.f, a3 = 0.f;
        for (int s = 0; s <= S; s++) {
            const float xv = sx[s * F + f];
            const float4 at = *(const float4*)(slog + s * 4);   // broadcast LDS.128
            a0 += at.x * xv; a1 += at.y * xv; a2 += at.z * xv; a3 += at.w * xv;
        }
        yo[0 * F + f] = a0; yo[1 * F + f] = a1; yo[2 * F + f] = a2; yo[3 * F + f] = a3;
    }
}

// ---------------- f32x2 tiled GEMM (round-2/4 proven; + cStrideH) ----------------
// C[h*cStrideH + m][h*cColPerH + n] = sum_k A[h*aStrideH + m*lda + k] * B[h*bStrideH + k*ldb + n]
template<int BM, int BN, int TM, int TN>
__global__ __launch_bounds__(256)
void gemm_f32x2(const float* __restrict__ A, const float* __restrict__ B,
                float* __restrict__ C,
                int K, int lda, int ldb, int ldc,
                int aStrideH, long bStrideH, int cColPerH, long cStrideH)
{
    constexpr int BK  = 16;
    constexpr int NT  = 256;
    constexpr int TX  = BN / TN;
    constexpr int MP  = TM / 2;
    constexpr int nA4 = BM * BK / 4 / NT;
    constexpr int nB4 = BK * BN / 4 / NT;

    const int h = blockIdx.z;
    A += (long)h * aStrideH;
    B += (long)h * bStrideH;
    C += (long)h * cStrideH;
    const int bm = blockIdx.x * BM;
    const int bn = blockIdx.y * BN;

    __shared__ float As[2][BK][BM];   // transposed A tile: As[k][m]
    __shared__ float Bs[2][BK][BN];

    const int tid = threadIdx.x;
    const int tx  = tid % TX;
    const int ty  = tid / TX;

    unsigned long long acc[MP][TN];
    #pragma unroll
    for (int i = 0; i < MP; i++)
        #pragma unroll
        for (int j = 0; j < TN; j++) acc[i][j] = 0ull;

    int arow[nA4], akq[nA4], bkk[nB4], bnn[nB4];
    #pragma unroll
    for (int i = 0; i < nA4; i++) {
        const int id = tid + i * NT;
        arow[i] = id / (BK / 4);
        akq[i]  = (id % (BK / 4)) * 4;
    }
    #pragma unroll
    for (int i = 0; i < nB4; i++) {
        const int id = tid + i * NT;
        bkk[i] = id / (BN / 4);
        bnn[i] = (id % (BN / 4)) * 4;
    }

    float4 ra[nA4], rb[nB4];
    const int nk = K / BK;

    auto ldg = [&](int kb) {
        #pragma unroll
        for (int i = 0; i < nA4; i++)
            ra[i] = *(const float4*)(A + (long)(bm + arow[i]) * lda + kb * BK + akq[i]);
        #pragma unroll
        for (int i = 0; i < nB4; i++)
            rb[i] = *(const float4*)(B + (long)(kb * BK + bkk[i]) * ldb + bn + bnn[i]);
    };
    auto sts = [&](int s) {
        #pragma unroll
        for (int i = 0; i < nA4; i++) {
            As[s][akq[i] + 0][arow[i]] = ra[i].x;
            As[s][akq[i] + 1][arow[i]] = ra[i].y;
            As[s][akq[i] + 2][arow[i]] = ra[i].z;
            As[s][akq[i] + 3][arow[i]] = ra[i].w;
        }
        #pragma unroll
        for (int i = 0; i < nB4; i++)
            *(float4*)&Bs[s][bkk[i]][bnn[i]] = rb[i];
    };
    auto compute = [&](int s) {
        #pragma unroll
        for (int k = 0; k < BK; k++) {
            float a[TM], b[TN];
            #pragma unroll
            for (int q = 0; q < TM / 4; q++)
                *(float4*)&a[q * 4] = *(const float4*)&As[s][k][ty * TM + q * 4];
            #pragma unroll
            for (int q = 0; q < TN / 4; q++)
                *(float4*)&b[q * 4] = *(const float4*)&Bs[s][k][tx * TN + q * 4];
            unsigned long long ap[MP], bp[TN];
            #pragma unroll
            for (int i = 0; i < MP; i++) ap[i] = pack2(a[2 * i], a[2 * i + 1]);
            #pragma unroll
            for (int j = 0; j < TN; j++) bp[j] = pack2(b[j], b[j]);
            #pragma unroll
            for (int i = 0; i < MP; i++)
                #pragma unroll
                for (int j = 0; j < TN; j++)
                    fma2(acc[i][j], ap[i], bp[j]);
        }
    };

    ldg(0);
    sts(0);
    __syncthreads();

    for (int kb = 0; kb < nk; kb++) {
        const int cur = kb & 1;
        if (kb + 1 < nk) ldg(kb + 1);
        compute(cur);
        if (kb + 1 < nk) {
            sts(cur ^ 1);
            __syncthreads();
        }
    }

    const int ccol = bn + h * cColPerH;
    #pragma unroll
    for (int ip = 0; ip < MP; ip++) {
        float lo[TN], hi[TN];
        #pragma unroll
        for (int j = 0; j < TN; j++) unpack2(acc[ip][j], lo[j], hi[j]);
        float* cr0 = C + (long)(bm + ty * TM + 2 * ip)     * ldc + ccol + tx * TN;
        float* cr1 = C + (long)(bm + ty * TM + 2 * ip + 1) * ldc + ccol + tx * TN;
        #pragma unroll
        for (int q = 0; q < TN / 4; q++) {
            *(float4*)(cr0 + q * 4) = make_float4(lo[q*4+0], lo[q*4+1], lo[q*4+2], lo[q*4+3]);
            *(float4*)(cr1 + q * 4) = make_float4(hi[q*4+0], hi[q*4+1], hi[q*4+2], hi[q*4+3]);
        }
    }
}

// ---------------- 4-way partial reduce ----------------
__global__ void reduce4(const float4* __restrict__ p, float4* __restrict__ out, int n4)
{
    const int i = blockIdx.x * blockDim.x + threadIdx.x;
    if (i < n4) {
        float4 a = p[i], b = p[i + n4], c = p[i + 2 * n4], d = p[i + 3 * n4];
        out[i] = make_float4(a.x + b.x + c.x + d.x, a.y + b.y + c.y + d.y,
                             a.z + b.z + c.z + d.z, a.w + b.w + c.w + d.w);
    }
}

// ---------------- launch ----------------
static float* sym_addr(const void* symbol)
{
    void* p = nullptr;
    cudaGetSymbolAddress(&p, symbol);
    return (float*)p;
}

extern "C" void kernel_launch(void* const* d_in, const int* in_sizes, int n_in,
                              void* d_out, int out_size)
{
    const float* x0  = (const float*)d_in[0];  // (B, 1, 256)
    const float* x1  = (const float*)d_in[1];  // (B, 10, 256)
    const float* x2  = (const float*)d_in[2];  // (B, 250, 256)
    const float* w0  = (const float*)d_in[3];  // (4, 256, 128)
    const float* a0s = (const float*)d_in[4];  // (4, 256)
    const float* a0n = (const float*)d_in[5];  // (4, 256)
    const float* w1  = (const float*)d_in[6];  // (4, 512, 128)
    const float* a1s = (const float*)d_in[7];  // (4, 512)
    const float* a1n = (const float*)d_in[8];  // (4, 512)
    const float* fcw = (const float*)d_in[9];  // (512, 256)
    float* out = (float*)d_out;                // (B, 256)

    const int Bn   = in_sizes[0] / 256;        // 1024
    const int nA   = Bn * 10;                  // 10240 level-1 nodes
    const int nTot = nA + Bn;                  // 11264

    float* y    = sym_addr(g_y);
    float* hb   = sym_addr(g_h);
    float* y2   = sym_addr(g_y2);
    float* W2   = sym_addr(g_W2);
    float* part = sym_addr(g_part);

    // ---- W2 precompute: W2[h] = w1[h] @ fcw[h*128:(h+1)*128, :]  (M=512,K=128,N=256) ----
    gemm_f32x2<64, 64, 4, 4><<<dim3(8, 4, NHEAD), 256>>>(
        w1, fcw, W2, 128, 128, 256, 256,
        /*aStrideH*/ 512 * 128, /*bStrideH*/ (long)128 * 256, /*cColPerH*/ 0, /*cStrideH*/ (long)512 * 256);

    // ---- layer-0 attention at both tree levels, one launch ----
    {
        const size_t smem = (size_t)(26 * 256 + 26 * 4 + 8) * sizeof(float);
        gat_attn<256><<<nTot, 256, smem>>>(x1, x2, 25, nA,
                                           x0, x1, 10,
                                           a0s, a0n, y);
    }
    // ---- layer-0 projection for all 11264 nodes: hb = y @ w0 (per head) ----
    gemm_f32x2<128, 128, 8, 8><<<dim3(nTot / 128, 1, NHEAD), 256>>>(
        y, w0, hb, 256, NHEAD * 256, 128, 512,
        /*aStrideH*/ 256, /*bStrideH*/ (long)256 * 128, /*cColPerH*/ 128, /*cStrideH*/ 0);

    // ---- layer-1 attention at root level ----
    {
        const size_t smem = (size_t)(11 * 512 + 11 * 4 + 8) * sizeof(float);
        gat_attn<512><<<Bn, 256, smem>>>(hb + (long)nA * 512, hb, 10, Bn,
                                         hb + (long)nA * 512, hb, 10,
                                         a1s, a1n, y2);
    }

    // ---- folded back-end: part[h] = y2[:,h,:] @ W2[h]  (M=1024,K=512,N=256 per head) ----
    gemm_f32x2<64, 64, 4, 4><<<dim3(Bn / 64, 4, NHEAD), 256>>>(
        y2, W2, part, 512, NHEAD * 512, 256, 256,
        /*aStrideH*/ 512, /*bStrideH*/ (long)512 * 256, /*cColPerH*/ 0, /*cStrideH*/ (long)Bn * 256);

    // ---- out = sum over heads ----
    const int n4 = Bn * 256 / 4;
    reduce4<<<(n4 + 255) / 256, 256>>>((const float4*)part, (float4*)out, n4);
}

// round 7
// speedup vs baseline: 2.6297x; 1.2055x over previous
#include <cuda_runtime.h>
#include <cuda_bf16.h>
#include <cstdint>

#define NHEAD 4
#define NEG_SLOPE 0.2f

// ---------------- scratch (allocation-free: __device__ globals) ----------------
__device__ float g_y   [11264 * NHEAD * 256];  // layer-0 aggregates (both levels)
__device__ float g_h   [11264 * 512];          // layer-0 outputs: h1 [0,10240), h0a [10240,11264)
__device__ float g_y2  [1024 * NHEAD * 512];   // layer-1 aggregates
__device__ float g_W2  [NHEAD * 512 * 256];    // folded weights: W2[h] = w1[h] @ fcw[h-slice]
__device__ float g_part[NHEAD * 1024 * 256];   // per-head partial outputs

// ---------------- f32x2 packed-math helpers ----------------
__device__ __forceinline__ unsigned long long pack2(float lo, float hi) {
    unsigned long long r;
    asm("mov.b64 %0, {%1,%2};" : "=l"(r) : "f"(lo), "f"(hi));
    return r;
}
__device__ __forceinline__ void unpack2(unsigned long long v, float& lo, float& hi) {
    asm("mov.b64 {%0,%1}, %2;" : "=f"(lo), "=f"(hi) : "l"(v));
}
__device__ __forceinline__ void fma2(unsigned long long& c, unsigned long long a,
                                     unsigned long long b) {
    asm("fma.rn.f32x2 %0, %1, %2, %0;" : "+l"(c) : "l"(a), "l"(b));
}

// ---------------- bf16 split helpers ----------------
// v = hi + lo (hi, lo bf16); returns packed pair of two consecutive values.
__device__ __forceinline__ uint32_t bfsplit2(float v0, float v1, uint32_t& lopk) {
    const unsigned short h0 = __bfloat16_as_ushort(__float2bfloat16_rn(v0));
    const unsigned short h1 = __bfloat16_as_ushort(__float2bfloat16_rn(v1));
    const float r0 = v0 - __bfloat162float(__ushort_as_bfloat16(h0));
    const float r1 = v1 - __bfloat162float(__ushort_as_bfloat16(h1));
    const unsigned short l0 = __bfloat16_as_ushort(__float2bfloat16_rn(r0));
    const unsigned short l1 = __bfloat16_as_ushort(__float2bfloat16_rn(r1));
    lopk = (uint32_t)l0 | ((uint32_t)l1 << 16);
    return (uint32_t)h0 | ((uint32_t)h1 << 16);
}

__device__ __forceinline__ void mma_bf16(float* d, const uint32_t* a, const uint32_t* b) {
    asm volatile(
        "mma.sync.aligned.m16n8k16.row.col.f32.bf16.bf16.f32 "
        "{%0,%1,%2,%3}, {%4,%5,%6,%7}, {%8,%9}, {%0,%1,%2,%3};"
        : "+f"(d[0]), "+f"(d[1]), "+f"(d[2]), "+f"(d[3])
        : "r"(a[0]), "r"(a[1]), "r"(a[2]), "r"(a[3]), "r"(b[0]), "r"(b[1]));
}

// ---------------- split-bf16 HMMA GEMM: hb = y @ w0 per head ----------------
// A row m of head h: y + m*1024 + h*256 (K=256). B = w0[h] (256x128 row-major).
// C = hb row m, cols h*128..h*128+127 (ldc=512).
// Tile BM=64, BN=128, BK=64; 8 warps (2 m x 4 n), warp tile 32x32.
#define LRow 72   // smem row stride in bf16 units (64 data + 8 pad -> conflict-free)

__global__ __launch_bounds__(256)
void gemm_hmma_l0(const float* __restrict__ A, const float* __restrict__ W,
                  float* __restrict__ C, int ldaH)
{
    extern __shared__ unsigned short smem[];
    unsigned short* AsH = smem;                  //  64 x 72
    unsigned short* AsL = smem + 64 * LRow;
    unsigned short* BsH = smem + 2 * 64 * LRow;  // 128 x 72 (layout [n][k])
    unsigned short* BsL = BsH + 128 * LRow;

    const int tid  = threadIdx.x;
    const int wid  = tid >> 5;
    const int lane = tid & 31;
    const int g    = lane >> 2;       // 0..7
    const int t    = lane & 3;        // 0..3
    const int wm   = (wid >> 2) * 32; // warp m offset (0/32)
    const int wn   = (wid & 3) * 32;  // warp n offset (0..96)

    const int m0 = blockIdx.x * 64;
    const int h  = blockIdx.y;
    const float* Wh = W + (long)h * 256 * 128;
    const float* Ah = A + (long)h * 256;

    float acc[2][4][4];
    #pragma unroll
    for (int i = 0; i < 2; i++)
        #pragma unroll
        for (int j = 0; j < 4; j++)
            #pragma unroll
            for (int q = 0; q < 4; q++) acc[i][j][q] = 0.f;

    for (int s = 0; s < 4; s++) {          // K chunks of 64
        const int k0 = s * 64;
        __syncthreads();                   // previous compute done with smem

        // ---- stage A: 64 rows x 64 k (f32 -> hi/lo bf16) ----
        #pragma unroll
        for (int i = 0; i < 4; i++) {
            const int idx = tid + i * 256;        // 0..1023
            const int row = idx >> 4;
            const int c4  = (idx & 15) * 4;
            const float4 v = *(const float4*)(Ah + (long)(m0 + row) * ldaH + k0 + c4);
            uint32_t lo0, lo1;
            const uint32_t hi0 = bfsplit2(v.x, v.y, lo0);
            const uint32_t hi1 = bfsplit2(v.z, v.w, lo1);
            *(uint2*)&AsH[row * LRow + c4] = make_uint2(hi0, hi1);
            *(uint2*)&AsL[row * LRow + c4] = make_uint2(lo0, lo1);
        }
        // ---- stage B transposed: Bs[n][k] = W[k0+k][n] ----
        {
            const int n  = tid & 127;
            const int kb = (tid >> 7) * 32;       // 0 or 32
            #pragma unroll
            for (int jq = 0; jq < 4; jq++) {      // 8 k's per group
                uint32_t hi[4], lo[4];
                #pragma unroll
                for (int j2 = 0; j2 < 4; j2++) {
                    const int k = k0 + kb + jq * 8 + j2 * 2;
                    const float v0 = Wh[(long)k * 128 + n];
                    const float v1 = Wh[(long)(k + 1) * 128 + n];
                    hi[j2] = bfsplit2(v0, v1, lo[j2]);
                }
                *(uint4*)&BsH[n * LRow + kb + jq * 8] = make_uint4(hi[0], hi[1], hi[2], hi[3]);
                *(uint4*)&BsL[n * LRow + kb + jq * 8] = make_uint4(lo[0], lo[1], lo[2], lo[3]);
            }
        }
        __syncthreads();

        // ---- compute: 4 x k16 steps ----
        #pragma unroll
        for (int kk = 0; kk < 64; kk += 16) {
            uint32_t ah[2][4], al[2][4];
            #pragma unroll
            for (int mt = 0; mt < 2; mt++) {
                const int r = wm + mt * 16;
                const int ca = kk + t * 2;
                ah[mt][0] = *(const uint32_t*)&AsH[(r + g)     * LRow + ca];
                ah[mt][1] = *(const uint32_t*)&AsH[(r + 8 + g) * LRow + ca];
                ah[mt][2] = *(const uint32_t*)&AsH[(r + g)     * LRow + ca + 8];
                ah[mt][3] = *(const uint32_t*)&AsH[(r + 8 + g) * LRow + ca + 8];
                al[mt][0] = *(const uint32_t*)&AsL[(r + g)     * LRow + ca];
                al[mt][1] = *(const uint32_t*)&AsL[(r + 8 + g) * LRow + ca];
                al[mt][2] = *(const uint32_t*)&AsL[(r + g)     * LRow + ca + 8];
                al[mt][3] = *(const uint32_t*)&AsL[(r + 8 + g) * LRow + ca + 8];
            }
            uint32_t bh[4][2], bl[4][2];
            #pragma unroll
            for (int nt = 0; nt < 4; nt++) {
                const int n = wn + nt * 8 + g;
                const int cb = kk + t * 2;
                bh[nt][0] = *(const uint32_t*)&BsH[n * LRow + cb];
                bh[nt][1] = *(const uint32_t*)&BsH[n * LRow + cb + 8];
                bl[nt][0] = *(const uint32_t*)&BsL[n * LRow + cb];
                bl[nt][1] = *(const uint32_t*)&BsL[n * LRow + cb + 8];
            }
            #pragma unroll
            for (int mt = 0; mt < 2; mt++)
                #pragma unroll
                for (int nt = 0; nt < 4; nt++) {
                    mma_bf16(acc[mt][nt], ah[mt], bh[nt]);  // hi*hi
                    mma_bf16(acc[mt][nt], ah[mt], bl[nt]);  // hi*lo
                    mma_bf16(acc[mt][nt], al[mt], bh[nt]);  // lo*hi
                }
        }
    }

    // ---- epilogue ----
    #pragma unroll
    for (int mt = 0; mt < 2; mt++)
        #pragma unroll
        for (int nt = 0; nt < 4; nt++) {
            const int r  = m0 + wm + mt * 16 + g;
            const int cc = h * 128 + wn + nt * 8 + t * 2;
            *(float2*)(C + (long)r * 512 + cc)       = make_float2(acc[mt][nt][0], acc[mt][nt][1]);
            *(float2*)(C + (long)(r + 8) * 512 + cc) = make_float2(acc[mt][nt][2], acc[mt][nt][3]);
        }
}

// ---------------- fused attention + aggregation (proven, low-LDS) ----------------
template <int F>
__global__ __launch_bounds__(256)
void gat_attn(const float* __restrict__ xsA, const float* __restrict__ xnA, int SA, int nA,
              const float* __restrict__ xsB, const float* __restrict__ xnB, int SB,
              const float* __restrict__ a_self, const float* __restrict__ a_neigh,
              float* __restrict__ y)
{
    constexpr int RCAP = (F == 256) ? 26 : 11;
    extern __shared__ float sm[];
    float* sx     = sm;
    float* slog   = sm + RCAP * F;
    float* slself = slog + RCAP * 4;

    const int tid = threadIdx.x;
    const int w = tid >> 5, l = tid & 31;
    const int item = blockIdx.x;

    const float* xs; const float* xn; int S;
    if (item < nA) { xs = xsA + (long)item * F;        xn = xnA + (long)item * SA * F;        S = SA; }
    else           { int b = item - nA;
                     xs = xsB + (long)b * F;           xn = xnB + (long)b * SB * F;           S = SB; }
    float* yo = y + (long)item * NHEAD * F;

    {
        const float4* s4 = (const float4*)xs;
        for (int i = tid; i < F / 4; i += 256) ((float4*)sx)[i] = s4[i];
        const float4* n4 = (const float4*)xn;
        float4* dst = (float4*)(sx + F);
        for (int i = tid; i < S * F / 4; i += 256) dst[i] = n4[i];
    }

    if (w == 0) {
        float sl[4] = {0.f, 0.f, 0.f, 0.f};
        for (int c = 0; c < F / 256; c++) {
            #pragma unroll
            for (int fi = 0; fi < 8; fi++) {
                const int f = c * 256 + l + fi * 32;
                const float xv = xs[f];
                sl[0] += xv * a_self[0 * F + f];
                sl[1] += xv * a_self[1 * F + f];
                sl[2] += xv * a_self[2 * F + f];
                sl[3] += xv * a_self[3 * F + f];
            }
        }
        #pragma unroll
        for (int h = 0; h < 4; h++) {
            float v = sl[h];
            #pragma unroll
            for (int o = 16; o; o >>= 1) v += __shfl_down_sync(0xffffffffu, v, o);
            if (l == 0) slself[h] = v;
        }
    }
    __syncthreads();

    {
        float lg[4][4] = {};
        for (int c = 0; c < F / 256; c++) {
            float avn[4][8];
            #pragma unroll
            for (int h = 0; h < 4; h++)
                #pragma unroll
                for (int fi = 0; fi < 8; fi++)
                    avn[h][fi] = a_neigh[h * F + c * 256 + l + fi * 32];
            #pragma unroll
            for (int ti = 0; ti < 4; ti++) {
                const int tt = w + ti * 8;
                if (tt <= S) {
                    const float* row = sx + tt * F + c * 256;
                    #pragma unroll
                    for (int fi = 0; fi < 8; fi++) {
                        const float xv = row[l + fi * 32];
                        lg[ti][0] += xv * avn[0][fi];
                        lg[ti][1] += xv * avn[1][fi];
                        lg[ti][2] += xv * avn[2][fi];
                        lg[ti][3] += xv * avn[3][fi];
                    }
                }
            }
        }
        #pragma unroll
        for (int ti = 0; ti < 4; ti++) {
            const int tt = w + ti * 8;
            #pragma unroll
            for (int h = 0; h < 4; h++) {
                float v = lg[ti][h];
                #pragma unroll
                for (int o = 16; o; o >>= 1) v += __shfl_down_sync(0xffffffffu, v, o);
                if (l == 0 && tt <= S) slog[tt * 4 + h] = v;
            }
        }
    }
    __syncthreads();

    if (tid < 32) {
        const bool act = (l <= S);
        float z[4];
        #pragma unroll
        for (int h = 0; h < 4; h++) {
            float v = act ? (slself[h] + slog[l * 4 + h]) : -1e30f;
            z[h] = (v >= 0.f) ? v : NEG_SLOPE * v;
        }
        #pragma unroll
        for (int h = 0; h < 4; h++) {
            float m = z[h];
            #pragma unroll
            for (int o = 16; o; o >>= 1) m = fmaxf(m, __shfl_xor_sync(0xffffffffu, m, o));
            const float ev = act ? __expf(z[h] - m) : 0.f;
            float s = ev;
            #pragma unroll
            for (int o = 16; o; o >>= 1) s += __shfl_xor_sync(0xffffffffu, s, o);
            if (act) slog[l * 4 + h] = ev / s;
        }
    }
    __syncthreads();

    for (int f = tid; f < F; f += 256) {
        float a0 = 0.f, a1 = 0.f, a2 = 0.f, a3 = 0.f;
        for (int s = 0; s <= S; s++) {
            const float xv = sx[s * F + f];
            const float4 at = *(const float4*)(slog + s * 4);
            a0 += at.x * xv; a1 += at.y * xv; a2 += at.z * xv; a3 += at.w * xv;
        }
        yo[0 * F + f] = a0; yo[1 * F + f] = a1; yo[2 * F + f] = a2; yo[3 * F + f] = a3;
    }
}

// ---------------- f32x2 tiled GEMM (proven) ----------------
template<int BM, int BN, int TM, int TN>
__global__ __launch_bounds__(256)
void gemm_f32x2(const float* __restrict__ A, const float* __restrict__ B,
                float* __restrict__ C,
                int K, int lda, int ldb, int ldc,
                int aStrideH, long bStrideH, int cColPerH, long cStrideH)
{
    constexpr int BK  = 16;
    constexpr int NT  = 256;
    constexpr int TX  = BN / TN;
    constexpr int MP  = TM / 2;
    constexpr int nA4 = BM * BK / 4 / NT;
    constexpr int nB4 = BK * BN / 4 / NT;

    const int h = blockIdx.z;
    A += (long)h * aStrideH;
    B += (long)h * bStrideH;
    C += (long)h * cStrideH;
    const int bm = blockIdx.x * BM;
    const int bn = blockIdx.y * BN;

    __shared__ float As[2][BK][BM];
    __shared__ float Bs[2][BK][BN];

    const int tid = threadIdx.x;
    const int tx  = tid % TX;
    const int ty  = tid / TX;

    unsigned long long acc[MP][TN];
    #pragma unroll
    for (int i = 0; i < MP; i++)
        #pragma unroll
        for (int j = 0; j < TN; j++) acc[i][j] = 0ull;

    int arow[nA4], akq[nA4], bkk[nB4], bnn[nB4];
    #pragma unroll
    for (int i = 0; i < nA4; i++) {
        const int id = tid + i * NT;
        arow[i] = id / (BK / 4);
        akq[i]  = (id % (BK / 4)) * 4;
    }
    #pragma unroll
    for (int i = 0; i < nB4; i++) {
        const int id = tid + i * NT;
        bkk[i] = id / (BN / 4);
        bnn[i] = (id % (BN / 4)) * 4;
    }

    float4 ra[nA4], rb[nB4];
    const int nk = K / BK;

    auto ldg = [&](int kb) {
        #pragma unroll
        for (int i = 0; i < nA4; i++)
            ra[i] = *(const float4*)(A + (long)(bm + arow[i]) * lda + kb * BK + akq[i]);
        #pragma unroll
        for (int i = 0; i < nB4; i++)
            rb[i] = *(const float4*)(B + (long)(kb * BK + bkk[i]) * ldb + bn + bnn[i]);
    };
    auto sts = [&](int s) {
        #pragma unroll
        for (int i = 0; i < nA4; i++) {
            As[s][akq[i] + 0][arow[i]] = ra[i].x;
            As[s][akq[i] + 1][arow[i]] = ra[i].y;
            As[s][akq[i] + 2][arow[i]] = ra[i].z;
            As[s][akq[i] + 3][arow[i]] = ra[i].w;
        }
        #pragma unroll
        for (int i = 0; i < nB4; i++)
            *(float4*)&Bs[s][bkk[i]][bnn[i]] = rb[i];
    };
    auto compute = [&](int s) {
        #pragma unroll
        for (int k = 0; k < BK; k++) {
            float a[TM], b[TN];
            #pragma unroll
            for (int q = 0; q < TM / 4; q++)
                *(float4*)&a[q * 4] = *(const float4*)&As[s][k][ty * TM + q * 4];
            #pragma unroll
            for (int q = 0; q < TN / 4; q++)
                *(float4*)&b[q * 4] = *(const float4*)&Bs[s][k][tx * TN + q * 4];
            unsigned long long ap[MP], bp[TN];
            #pragma unroll
            for (int i = 0; i < MP; i++) ap[i] = pack2(a[2 * i], a[2 * i + 1]);
            #pragma unroll
            for (int j = 0; j < TN; j++) bp[j] = pack2(b[j], b[j]);
            #pragma unroll
            for (int i = 0; i < MP; i++)
                #pragma unroll
                for (int j = 0; j < TN; j++)
                    fma2(acc[i][j], ap[i], bp[j]);
        }
    };

    ldg(0);
    sts(0);
    __syncthreads();

    for (int kb = 0; kb < nk; kb++) {
        const int cur = kb & 1;
        if (kb + 1 < nk) ldg(kb + 1);
        compute(cur);
        if (kb + 1 < nk) {
            sts(cur ^ 1);
            __syncthreads();
        }
    }

    const int ccol = bn + h * cColPerH;
    #pragma unroll
    for (int ip = 0; ip < MP; ip++) {
        float lo[TN], hi[TN];
        #pragma unroll
        for (int j = 0; j < TN; j++) unpack2(acc[ip][j], lo[j], hi[j]);
        float* cr0 = C + (long)(bm + ty * TM + 2 * ip)     * ldc + ccol + tx * TN;
        float* cr1 = C + (long)(bm + ty * TM + 2 * ip + 1) * ldc + ccol + tx * TN;
        #pragma unroll
        for (int q = 0; q < TN / 4; q++) {
            *(float4*)(cr0 + q * 4) = make_float4(lo[q*4+0], lo[q*4+1], lo[q*4+2], lo[q*4+3]);
            *(float4*)(cr1 + q * 4) = make_float4(hi[q*4+0], hi[q*4+1], hi[q*4+2], hi[q*4+3]);
        }
    }
}

// ---------------- 4-way partial reduce ----------------
__global__ void reduce4(const float4* __restrict__ p, float4* __restrict__ out, int n4)
{
    const int i = blockIdx.x * blockDim.x + threadIdx.x;
    if (i < n4) {
        float4 a = p[i], b = p[i + n4], c = p[i + 2 * n4], d = p[i + 3 * n4];
        out[i] = make_float4(a.x + b.x + c.x + d.x, a.y + b.y + c.y + d.y,
                             a.z + b.z + c.z + d.z, a.w + b.w + c.w + d.w);
    }
}

// ---------------- launch ----------------
static float* sym_addr(const void* symbol)
{
    void* p = nullptr;
    cudaGetSymbolAddress(&p, symbol);
    return (float*)p;
}

extern "C" void kernel_launch(void* const* d_in, const int* in_sizes, int n_in,
                              void* d_out, int out_size)
{
    const float* x0  = (const float*)d_in[0];
    const float* x1  = (const float*)d_in[1];
    const float* x2  = (const float*)d_in[2];
    const float* w0  = (const float*)d_in[3];
    const float* a0s = (const float*)d_in[4];
    const float* a0n = (const float*)d_in[5];
    const float* w1  = (const float*)d_in[6];
    const float* a1s = (const float*)d_in[7];
    const float* a1n = (const float*)d_in[8];
    const float* fcw = (const float*)d_in[9];
    float* out = (float*)d_out;

    const int Bn   = in_sizes[0] / 256;        // 1024
    const int nA   = Bn * 10;                  // 10240
    const int nTot = nA + Bn;                  // 11264

    float* y    = sym_addr(g_y);
    float* hb   = sym_addr(g_h);
    float* y2   = sym_addr(g_y2);
    float* W2   = sym_addr(g_W2);
    float* part = sym_addr(g_part);

    // ---- W2 precompute: W2[h] = w1[h] @ fcw[h*128:(h+1)*128, :] ----
    gemm_f32x2<64, 64, 4, 4><<<dim3(8, 4, NHEAD), 256>>>(
        w1, fcw, W2, 128, 128, 256, 256,
        512 * 128, (long)128 * 256, 0, (long)512 * 256);

    // ---- layer-0 attention at both tree levels ----
    {
        const size_t smem = (size_t)(26 * 256 + 26 * 4 + 8) * sizeof(float);
        gat_attn<256><<<nTot, 256, smem>>>(x1, x2, 25, nA,
                                           x0, x1, 10,
                                           a0s, a0n, y);
    }

    // ---- layer-0 projection (HMMA, split-bf16): hb = y @ w0 per head ----
    {
        const int smemB = (2 * 64 + 2 * 128) * LRow * 2;   // 55296 bytes
        static int cfgd = 0;
        if (!cfgd) {
            cudaFuncSetAttribute(gemm_hmma_l0, cudaFuncAttributeMaxDynamicSharedMemorySize, smemB);
            cfgd = 1;
        }
        gemm_hmma_l0<<<dim3(nTot / 64, NHEAD), 256, smemB>>>(y, w0, hb, NHEAD * 256);
    }

    // ---- layer-1 attention at root level ----
    {
        const size_t smem = (size_t)(11 * 512 + 11 * 4 + 8) * sizeof(float);
        gat_attn<512><<<Bn, 256, smem>>>(hb + (long)nA * 512, hb, 10, Bn,
                                         hb + (long)nA * 512, hb, 10,
                                         a1s, a1n, y2);
    }

    // ---- folded back-end: part[h] = y2[:,h,:] @ W2[h] ----
    gemm_f32x2<64, 64, 4, 4><<<dim3(Bn / 64, 4, NHEAD), 256>>>(
        y2, W2, part, 512, NHEAD * 512, 256, 256,
        512, (long)512 * 256, 0, (long)Bn * 256);

    // ---- out = sum over heads ----
    const int n4 = Bn * 256 / 4;
    reduce4<<<(n4 + 255) / 256, 256>>>((const float4*)part, (float4*)out, n4);
}

// round 8
// speedup vs baseline: 2.8823x; 1.0961x over previous
#include <cuda_runtime.h>
#include <cuda_bf16.h>
#include <cstdint>

#define NHEAD 4
#define NEG_SLOPE 0.2f

// ---------------- scratch (allocation-free: __device__ globals) ----------------
__device__ float g_y   [11264 * NHEAD * 256];  // layer-0 aggregates (both levels)
__device__ float g_h   [11264 * 512];          // layer-0 outputs: h1 [0,10240), h0a [10240,11264)
__device__ float g_y2  [1024 * NHEAD * 512];   // layer-1 aggregates
__device__ float g_W2  [NHEAD * 512 * 256];    // folded weights: W2[h] = w1[h] @ fcw[h-slice]
__device__ float g_part[NHEAD * 1024 * 256];   // per-head partial outputs

// ---------------- cp.async helpers ----------------
__device__ __forceinline__ uint32_t smem_u32(const void* p) {
    uint32_t a;
    asm("{ .reg .u64 t; cvta.to.shared.u64 t, %1; cvt.u32.u64 %0, t; }" : "=r"(a) : "l"(p));
    return a;
}
#define CP16(d, s)  asm volatile("cp.async.cg.shared.global [%0], [%1], 16;" :: "r"(d), "l"(s))
#define CP_COMMIT() asm volatile("cp.async.commit_group;" ::: "memory")
#define CP_WAIT0()  asm volatile("cp.async.wait_group 0;" ::: "memory")

// ---------------- bf16 split helpers ----------------
__device__ __forceinline__ uint32_t bfsplit2(float v0, float v1, uint32_t& lopk) {
    const unsigned short h0 = __bfloat16_as_ushort(__float2bfloat16_rn(v0));
    const unsigned short h1 = __bfloat16_as_ushort(__float2bfloat16_rn(v1));
    const float r0 = v0 - __bfloat162float(__ushort_as_bfloat16(h0));
    const float r1 = v1 - __bfloat162float(__ushort_as_bfloat16(h1));
    const unsigned short l0 = __bfloat16_as_ushort(__float2bfloat16_rn(r0));
    const unsigned short l1 = __bfloat16_as_ushort(__float2bfloat16_rn(r1));
    lopk = (uint32_t)l0 | ((uint32_t)l1 << 16);
    return (uint32_t)h0 | ((uint32_t)h1 << 16);
}

__device__ __forceinline__ void mma_bf16(float* d, const uint32_t* a, const uint32_t* b) {
    asm volatile(
        "mma.sync.aligned.m16n8k16.row.col.f32.bf16.bf16.f32 "
        "{%0,%1,%2,%3}, {%4,%5,%6,%7}, {%8,%9}, {%0,%1,%2,%3};"
        : "+f"(d[0]), "+f"(d[1]), "+f"(d[2]), "+f"(d[3])
        : "r"(a[0]), "r"(a[1]), "r"(a[2]), "r"(a[3]), "r"(b[0]), "r"(b[1]));
}

// ---------------- generalized split-bf16 HMMA GEMM ----------------
// C[h][m][bn+n] = sum_k A[h][m][k] * W[h][k][bn+n]
//   A element: A + h*aHeadStride + m*lda + k
//   W element: W + h*wHeadStride + k*ldw + n
//   C element: C + h*cHeadStride + m*ldc + n
// Tile BM=64, BN=128 (blockIdx.y selects n-block), BK=64; 8 warps, 32x32 warp tiles.
#define LRow 72   // smem row stride in bf16 units (64 data + 8 pad)

__global__ __launch_bounds__(256)
void gemm_hmma(const float* __restrict__ A, const float* __restrict__ W,
               float* __restrict__ C,
               int K, int lda, long aHeadStride,
               int ldw, long wHeadStride,
               int ldc, long cHeadStride)
{
    extern __shared__ unsigned short smem[];
    unsigned short* AsH = smem;                  //  64 x 72
    unsigned short* AsL = smem + 64 * LRow;
    unsigned short* BsH = smem + 2 * 64 * LRow;  // 128 x 72 (layout [n][k])
    unsigned short* BsL = BsH + 128 * LRow;

    const int tid  = threadIdx.x;
    const int wid  = tid >> 5;
    const int lane = tid & 31;
    const int g    = lane >> 2;
    const int t    = lane & 3;
    const int wm   = (wid >> 2) * 32;
    const int wn   = (wid & 3) * 32;

    const int m0 = blockIdx.x * 64;
    const int bn = blockIdx.y * 128;
    const int h  = blockIdx.z;
    const float* Ah = A + (long)h * aHeadStride;
    const float* Wh = W + (long)h * wHeadStride;
    float*       Ch = C + (long)h * cHeadStride;

    float acc[2][4][4];
    #pragma unroll
    for (int i = 0; i < 2; i++)
        #pragma unroll
        for (int j = 0; j < 4; j++)
            #pragma unroll
            for (int q = 0; q < 4; q++) acc[i][j][q] = 0.f;

    const int nChunks = K >> 6;
    for (int s = 0; s < nChunks; s++) {
        const int k0 = s * 64;
        __syncthreads();

        // ---- stage A: 64 rows x 64 k (f32 -> hi/lo bf16) ----
        #pragma unroll
        for (int i = 0; i < 4; i++) {
            const int idx = tid + i * 256;
            const int row = idx >> 4;
            const int c4  = (idx & 15) * 4;
            const float4 v = *(const float4*)(Ah + (long)(m0 + row) * lda + k0 + c4);
            uint32_t lo0, lo1;
            const uint32_t hi0 = bfsplit2(v.x, v.y, lo0);
            const uint32_t hi1 = bfsplit2(v.z, v.w, lo1);
            *(uint2*)&AsH[row * LRow + c4] = make_uint2(hi0, hi1);
            *(uint2*)&AsL[row * LRow + c4] = make_uint2(lo0, lo1);
        }
        // ---- stage B transposed: Bs[n][k] = W[k0+k][bn+n] ----
        {
            const int n  = tid & 127;
            const int kb = (tid >> 7) * 32;
            #pragma unroll
            for (int jq = 0; jq < 4; jq++) {
                uint32_t hi[4], lo[4];
                #pragma unroll
                for (int j2 = 0; j2 < 4; j2++) {
                    const int k = k0 + kb + jq * 8 + j2 * 2;
                    const float v0 = Wh[(long)k * ldw + bn + n];
                    const float v1 = Wh[(long)(k + 1) * ldw + bn + n];
                    hi[j2] = bfsplit2(v0, v1, lo[j2]);
                }
                *(uint4*)&BsH[n * LRow + kb + jq * 8] = make_uint4(hi[0], hi[1], hi[2], hi[3]);
                *(uint4*)&BsL[n * LRow + kb + jq * 8] = make_uint4(lo[0], lo[1], lo[2], lo[3]);
            }
        }
        __syncthreads();

        // ---- compute: 4 x k16 steps, 3 split terms each ----
        #pragma unroll
        for (int kk = 0; kk < 64; kk += 16) {
            uint32_t ah[2][4], al[2][4];
            #pragma unroll
            for (int mt = 0; mt < 2; mt++) {
                const int r = wm + mt * 16;
                const int ca = kk + t * 2;
                ah[mt][0] = *(const uint32_t*)&AsH[(r + g)     * LRow + ca];
                ah[mt][1] = *(const uint32_t*)&AsH[(r + 8 + g) * LRow + ca];
                ah[mt][2] = *(const uint32_t*)&AsH[(r + g)     * LRow + ca + 8];
                ah[mt][3] = *(const uint32_t*)&AsH[(r + 8 + g) * LRow + ca + 8];
                al[mt][0] = *(const uint32_t*)&AsL[(r + g)     * LRow + ca];
                al[mt][1] = *(const uint32_t*)&AsL[(r + 8 + g) * LRow + ca];
                al[mt][2] = *(const uint32_t*)&AsL[(r + g)     * LRow + ca + 8];
                al[mt][3] = *(const uint32_t*)&AsL[(r + 8 + g) * LRow + ca + 8];
            }
            uint32_t bh[4][2], bl[4][2];
            #pragma unroll
            for (int nt = 0; nt < 4; nt++) {
                const int n = wn + nt * 8 + g;
                const int cb = kk + t * 2;
                bh[nt][0] = *(const uint32_t*)&BsH[n * LRow + cb];
                bh[nt][1] = *(const uint32_t*)&BsH[n * LRow + cb + 8];
                bl[nt][0] = *(const uint32_t*)&BsL[n * LRow + cb];
                bl[nt][1] = *(const uint32_t*)&BsL[n * LRow + cb + 8];
            }
            #pragma unroll
            for (int mt = 0; mt < 2; mt++)
                #pragma unroll
                for (int nt = 0; nt < 4; nt++) {
                    mma_bf16(acc[mt][nt], ah[mt], bh[nt]);
                    mma_bf16(acc[mt][nt], ah[mt], bl[nt]);
                    mma_bf16(acc[mt][nt], al[mt], bh[nt]);
                }
        }
    }

    // ---- epilogue ----
    #pragma unroll
    for (int mt = 0; mt < 2; mt++)
        #pragma unroll
        for (int nt = 0; nt < 4; nt++) {
            const int r  = m0 + wm + mt * 16 + g;
            const int cc = bn + wn + nt * 8 + t * 2;
            *(float2*)(Ch + (long)r * ldc + cc)       = make_float2(acc[mt][nt][0], acc[mt][nt][1]);
            *(float2*)(Ch + (long)(r + 8) * ldc + cc) = make_float2(acc[mt][nt][2], acc[mt][nt][3]);
        }
}

// ---------------- fused attention + aggregation (proven; cp.async staging) ----------------
template <int F>
__global__ __launch_bounds__(256)
void gat_attn(const float* __restrict__ xsA, const float* __restrict__ xnA, int SA, int nA,
              const float* __restrict__ xsB, const float* __restrict__ xnB, int SB,
              const float* __restrict__ a_self, const float* __restrict__ a_neigh,
              float* __restrict__ y)
{
    constexpr int RCAP = (F == 256) ? 26 : 11;
    extern __shared__ float sm[];
    float* sx     = sm;
    float* slog   = sm + RCAP * F;
    float* slself = slog + RCAP * 4;

    const int tid = threadIdx.x;
    const int w = tid >> 5, l = tid & 31;
    const int item = blockIdx.x;

    const float* xs; const float* xn; int S;
    if (item < nA) { xs = xsA + (long)item * F;        xn = xnA + (long)item * SA * F;        S = SA; }
    else           { int b = item - nA;
                     xs = xsB + (long)b * F;           xn = xnB + (long)b * SB * F;           S = SB; }
    float* yo = y + (long)item * NHEAD * F;

    // stage x_all = [self; neighbors] via cp.async (bypasses register staging)
    {
        const uint32_t sx_u = smem_u32(sx);
        const float4* s4 = (const float4*)xs;
        for (int i = tid; i < F / 4; i += 256) CP16(sx_u + i * 16, s4 + i);
        const float4* n4 = (const float4*)xn;
        for (int i = tid; i < S * F / 4; i += 256) CP16(sx_u + (F / 4 + i) * 16, n4 + i);
        CP_COMMIT();
    }

    // self logits (warp 0, straight from global — overlaps cp.async drain)
    if (w == 0) {
        float sl[4] = {0.f, 0.f, 0.f, 0.f};
        for (int c = 0; c < F / 256; c++) {
            #pragma unroll
            for (int fi = 0; fi < 8; fi++) {
                const int f = c * 256 + l + fi * 32;
                const float xv = xs[f];
                sl[0] += xv * a_self[0 * F + f];
                sl[1] += xv * a_self[1 * F + f];
                sl[2] += xv * a_self[2 * F + f];
                sl[3] += xv * a_self[3 * F + f];
            }
        }
        #pragma unroll
        for (int h = 0; h < 4; h++) {
            float v = sl[h];
            #pragma unroll
            for (int o = 16; o; o >>= 1) v += __shfl_down_sync(0xffffffffu, v, o);
            if (l == 0) slself[h] = v;
        }
    }
    CP_WAIT0();
    __syncthreads();

    // neighbor-side logits (a_neigh in registers)
    {
        float lg[4][4] = {};
        for (int c = 0; c < F / 256; c++) {
            float avn[4][8];
            #pragma unroll
            for (int h = 0; h < 4; h++)
                #pragma unroll
                for (int fi = 0; fi < 8; fi++)
                    avn[h][fi] = a_neigh[h * F + c * 256 + l + fi * 32];
            #pragma unroll
            for (int ti = 0; ti < 4; ti++) {
                const int tt = w + ti * 8;
                if (tt <= S) {
                    const float* row = sx + tt * F + c * 256;
                    #pragma unroll
                    for (int fi = 0; fi < 8; fi++) {
                        const float xv = row[l + fi * 32];
                        lg[ti][0] += xv * avn[0][fi];
                        lg[ti][1] += xv * avn[1][fi];
                        lg[ti][2] += xv * avn[2][fi];
                        lg[ti][3] += xv * avn[3][fi];
                    }
                }
            }
        }
        #pragma unroll
        for (int ti = 0; ti < 4; ti++) {
            const int tt = w + ti * 8;
            #pragma unroll
            for (int h = 0; h < 4; h++) {
                float v = lg[ti][h];
                #pragma unroll
                for (int o = 16; o; o >>= 1) v += __shfl_down_sync(0xffffffffu, v, o);
                if (l == 0 && tt <= S) slog[tt * 4 + h] = v;
            }
        }
    }
    __syncthreads();

    // leaky-relu + softmax over S+1 (one warp, lane = s)
    if (tid < 32) {
        const bool act = (l <= S);
        float z[4];
        #pragma unroll
        for (int h = 0; h < 4; h++) {
            float v = act ? (slself[h] + slog[l * 4 + h]) : -1e30f;
            z[h] = (v >= 0.f) ? v : NEG_SLOPE * v;
        }
        #pragma unroll
        for (int h = 0; h < 4; h++) {
            float m = z[h];
            #pragma unroll
            for (int o = 16; o; o >>= 1) m = fmaxf(m, __shfl_xor_sync(0xffffffffu, m, o));
            const float ev = act ? __expf(z[h] - m) : 0.f;
            float s = ev;
            #pragma unroll
            for (int o = 16; o; o >>= 1) s += __shfl_xor_sync(0xffffffffu, s, o);
            if (act) slog[l * 4 + h] = ev / s;
        }
    }
    __syncthreads();

    // aggregation: y[h][f] = sum_s attn[s][h] * x_all[s][f]
    for (int f = tid; f < F; f += 256) {
        float a0 = 0.f, a1 = 0.f, a2 = 0.f, a3 = 0.f;
        for (int s = 0; s <= S; s++) {
            const float xv = sx[s * F + f];
            const float4 at = *(const float4*)(slog + s * 4);
            a0 += at.x * xv; a1 += at.y * xv; a2 += at.z * xv; a3 += at.w * xv;
        }
        yo[0 * F + f] = a0; yo[1 * F + f] = a1; yo[2 * F + f] = a2; yo[3 * F + f] = a3;
    }
}

// ---------------- 4-way partial reduce ----------------
__global__ void reduce4(const float4* __restrict__ p, float4* __restrict__ out, int n4)
{
    const int i = blockIdx.x * blockDim.x + threadIdx.x;
    if (i < n4) {
        float4 a = p[i], b = p[i + n4], c = p[i + 2 * n4], d = p[i + 3 * n4];
        out[i] = make_float4(a.x + b.x + c.x + d.x, a.y + b.y + c.y + d.y,
                             a.z + b.z + c.z + d.z, a.w + b.w + c.w + d.w);
    }
}

// ---------------- launch ----------------
static float* sym_addr(const void* symbol)
{
    void* p = nullptr;
    cudaGetSymbolAddress(&p, symbol);
    return (float*)p;
}

extern "C" void kernel_launch(void* const* d_in, const int* in_sizes, int n_in,
                              void* d_out, int out_size)
{
    const float* x0  = (const float*)d_in[0];
    const float* x1  = (const float*)d_in[1];
    const float* x2  = (const float*)d_in[2];
    const float* w0  = (const float*)d_in[3];
    const float* a0s = (const float*)d_in[4];
    const float* a0n = (const float*)d_in[5];
    const float* w1  = (const float*)d_in[6];
    const float* a1s = (const float*)d_in[7];
    const float* a1n = (const float*)d_in[8];
    const float* fcw = (const float*)d_in[9];
    float* out = (float*)d_out;

    const int Bn   = in_sizes[0] / 256;        // 1024
    const int nA   = Bn * 10;                  // 10240
    const int nTot = nA + Bn;                  // 11264

    float* y    = sym_addr(g_y);
    float* hb   = sym_addr(g_h);
    float* y2   = sym_addr(g_y2);
    float* W2   = sym_addr(g_W2);
    float* part = sym_addr(g_part);

    const int smemB = (2 * 64 + 2 * 128) * LRow * 2;   // 55296 bytes
    cudaFuncSetAttribute(gemm_hmma, cudaFuncAttributeMaxDynamicSharedMemorySize, smemB);

    // ---- W2 precompute: W2[h] = w1[h] @ fcw[h*128:(h+1)*128, :]  (M=512,K=128,N=256) ----
    gemm_hmma<<<dim3(8, 2, NHEAD), 256, smemB>>>(
        w1, fcw, W2, 128,
        /*lda*/128, /*aHead*/(long)512 * 128,
        /*ldw*/256, /*wHead*/(long)128 * 256,
        /*ldc*/256, /*cHead*/(long)512 * 256);

    // ---- layer-0 attention at both tree levels ----
    {
        const size_t smem = (size_t)(26 * 256 + 26 * 4 + 8) * sizeof(float);
        gat_attn<256><<<nTot, 256, smem>>>(x1, x2, 25, nA,
                                           x0, x1, 10,
                                           a0s, a0n, y);
    }

    // ---- layer-0 projection: hb = y @ w0 per head  (M=11264,K=256,N=128) ----
    gemm_hmma<<<dim3(nTot / 64, 1, NHEAD), 256, smemB>>>(
        y, w0, hb, 256,
        /*lda*/NHEAD * 256, /*aHead*/256,
        /*ldw*/128, /*wHead*/(long)256 * 128,
        /*ldc*/512, /*cHead*/128);

    // ---- layer-1 attention at root level ----
    {
        const size_t smem = (size_t)(11 * 512 + 11 * 4 + 8) * sizeof(float);
        gat_attn<512><<<Bn, 256, smem>>>(hb + (long)nA * 512, hb, 10, Bn,
                                         hb + (long)nA * 512, hb, 10,
                                         a1s, a1n, y2);
    }

    // ---- folded back-end: part[h] = y2[:,h,:] @ W2[h]  (M=1024,K=512,N=256) ----
    gemm_hmma<<<dim3(Bn / 64, 2, NHEAD), 256, smemB>>>(
        y2, W2, part, 512,
        /*lda*/NHEAD * 512, /*aHead*/512,
        /*ldw*/256, /*wHead*/(long)512 * 256,
        /*ldc*/256, /*cHead*/(long)Bn * 256);

    // ---- out = sum over heads ----
    const int n4 = Bn * 256 / 4;
    reduce4<<<(n4 + 255) / 256, 256>>>((const float4*)part, (float4*)out, n4);
}